// round 3
// baseline (speedup 1.0000x reference)
#include <cuda_runtime.h>

#define CB 32
#define CT 1024
#define CS 256
#define CN 80
#define TTILE 64

#define NEGF (-3.4028234663852886e38f)   // jnp.finfo(float32).min == -FLT_MAX
#define LOG2PI_F 1.8378770664093453f

// Scratch (global __device__ arrays are the allowed scratch mechanism)
static __device__ float g_ll[(size_t)CB * CT * CS];   // 33.5 MB masked log-likelihood
static __device__ int   g_idx[CB * CT];               // backtracked argmax index per (b,t)

// ---------------------------------------------------------------------------
// Kernel A: ll[b,t,s] = -0.5*(log(2pi) + |lat|^2 - 2*lat.mean + |mean|^2) * attnmask
// Tiled: one block per (b, 64-row t-chunk). Shared tiles transposed (n-major)
// for conflict-free broadcast reads. 4(t) x 16(s) register blocking per thread.
// ---------------------------------------------------------------------------
__global__ __launch_bounds__(256, 1)
void kernelA(const float* __restrict__ latent, const float* __restrict__ mean,
             const int* __restrict__ textlen, const int* __restrict__ mellen)
{
    extern __shared__ float sh[];
    float* smean  = sh;                          // [CN][CS+1]
    float* slat   = smean + CN * (CS + 1);       // [CN][TTILE+1]
    float* smean2 = slat + CN * (TTILE + 1);     // [CS]
    float* slat2  = smean2 + CS;                 // [TTILE]

    const int b     = blockIdx.x >> 4;           // 16 t-chunks per batch
    const int tc    = blockIdx.x & 15;
    const int tid   = threadIdx.x;
    const int tbase = tc * TTILE;

    // Load mean[b] transposed into shared (coalesced global reads)
    for (int idx = tid; idx < CS * CN; idx += 256) {
        int s = idx / CN, n = idx - s * CN;
        smean[n * (CS + 1) + s] = mean[(b * CS + s) * CN + n];
    }
    // Load latent tile transposed
    for (int idx = tid; idx < TTILE * CN; idx += 256) {
        int tl = idx / CN, n = idx - tl * CN;
        slat[n * (TTILE + 1) + tl] = latent[((size_t)(b * CT + tbase + tl)) * CN + n];
    }
    __syncthreads();

    // Row norms, sequential fp32 (square rounded, then added — mirrors sum(square))
    {
        float acc = 0.f;
        #pragma unroll 4
        for (int n = 0; n < CN; n++) {
            float v = smean[n * (CS + 1) + tid];
            acc = __fadd_rn(acc, __fmul_rn(v, v));
        }
        smean2[tid] = acc;
    }
    if (tid < TTILE) {
        float acc = 0.f;
        #pragma unroll 4
        for (int n = 0; n < CN; n++) {
            float v = slat[n * (TTILE + 1) + tid];
            acc = __fadd_rn(acc, __fmul_rn(v, v));
        }
        slat2[tid] = acc;
    }
    __syncthreads();

    const int tx = tid & 15;    // s lane: covers s = tx + 16*i
    const int ty = tid >> 4;    // t group: covers t = ty*4 + j

    float acc[4][16];
    #pragma unroll
    for (int j = 0; j < 4; j++)
        #pragma unroll
        for (int i = 0; i < 16; i++) acc[j][i] = 0.f;

    const float* mrow = smean + tx;
    const float* arow = slat + ty * 4;

    #pragma unroll 2
    for (int n = 0; n < CN; n++) {
        float a[4], m[16];
        #pragma unroll
        for (int j = 0; j < 4; j++) a[j] = arow[n * (TTILE + 1) + j];
        #pragma unroll
        for (int i = 0; i < 16; i++) m[i] = mrow[n * (CS + 1) + 16 * i];
        #pragma unroll
        for (int j = 0; j < 4; j++)
            #pragma unroll
            for (int i = 0; i < 16; i++)
                acc[j][i] = __fmaf_rn(a[j], m[i], acc[j][i]);
    }

    const int tl_b = textlen[b];
    const int ml_b = mellen[b];
    #pragma unroll
    for (int j = 0; j < 4; j++) {
        int tl = ty * 4 + j;
        int tg = tbase + tl;
        float l2 = slat2[tl];
        float rowmask = (tg < ml_b) ? 1.f : 0.f;
        float* outrow = g_ll + ((size_t)(b * CT + tg)) * CS;
        #pragma unroll
        for (int i = 0; i < 16; i++) {
            int s = tx + 16 * i;
            float dist = __fadd_rn(__fmaf_rn(-2.f, acc[j][i], l2), smean2[s]);
            float msk  = (s < tl_b) ? rowmask : 0.f;
            float ll   = __fmul_rn(__fmul_rn(-0.5f, __fadd_rn(LOG2PI_F, dist)), msk);
            outrow[s] = ll;
        }
    }
}

// ---------------------------------------------------------------------------
// Kernel B: Viterbi forward (sequential over T) + fused backtrack.
// One warp per batch; lane owns 8 contiguous s. Neighbor via shuffle.
// ll rows prefetched 4-deep (L2-resident). Direction bits in shared (32KB).
// ---------------------------------------------------------------------------
__global__ __launch_bounds__(32, 1)
void kernelB(const int* __restrict__ textlen, const int* __restrict__ mellen)
{
    __shared__ unsigned char sdir[CT * 32];   // 1 byte per (t, lane) = 8 dir bits

    const int b    = blockIdx.x;
    const int lane = threadIdx.x;
    const int tl_b = textlen[b];
    const int ml_b = mellen[b];

    float prob[8];
    #pragma unroll
    for (int k = 0; k < 8; k++) prob[k] = 0.f;

    const float4* base = (const float4*)(g_ll + (size_t)b * CT * CS);
    const int roff = lane * 2;   // 2 float4 per lane per row

    float4 bufA[4], bufB[4];
    #pragma unroll
    for (int p = 0; p < 4; p++) {
        bufA[p] = base[p * (CS / 4) + roff];
        bufB[p] = base[p * (CS / 4) + roff + 1];
    }

    for (int t0 = 0; t0 < CT; t0 += 4) {
        #pragma unroll
        for (int u = 0; u < 4; u++) {
            const int t = t0 + u;
            float4 lo = bufA[u], hi = bufB[u];
            int tp = t + 4;
            if (tp < CT) {                     // prefetch 4 rows ahead
                bufA[u] = base[tp * (CS / 4) + roff];
                bufB[u] = base[tp * (CS / 4) + roff + 1];
            }
            float llv[8] = {lo.x, lo.y, lo.z, lo.w, hi.x, hi.y, hi.z, hi.w};

            float prevv = __shfl_up_sync(0xffffffffu, prob[7], 1);
            if (lane == 0) prevv = NEGF;

            unsigned bits = 0;
            const bool tm = (t < ml_b);
            #pragma unroll
            for (int k = 0; k < 8; k++) {
                float cur = prob[k];
                bool  mk  = (cur >= prevv);              // stay if prob >= prev
                float pm  = mk ? cur : prevv;
                int   s   = (lane << 3) + k;
                prob[k]   = (s <= t) ? __fadd_rn(pm, llv[k]) : NEGF;
                unsigned d = (tm && (s < tl_b)) ? (mk ? 1u : 0u) : 1u;
                bits |= d << k;
                prevv = cur;                             // old prob[k] for next k
            }
            sdir[t * 32 + lane] = (unsigned char)bits;
        }
    }
    __syncwarp();

    // Backtrack (sequential pointer-chase through shared dir bits)
    if (lane == 0) {
        int idx = tl_b - 1;
        int* gout = g_idx + b * CT;
        #pragma unroll 4
        for (int t = CT - 1; t >= 0; t--) {
            gout[t] = idx;
            unsigned by = sdir[t * 32 + (idx >> 3)];
            idx += (int)((by >> (idx & 7)) & 1u) - 1;    // dir=1 stay, dir=0 step down
        }
    }
}

// ---------------------------------------------------------------------------
// Kernel C: write residual [B,T,N] then attn [B,T,S] into d_out (float4).
// residual = latent - mean[b, s*(t)]   (or latent where t >= mellen)
// attn[b,t,s] = (s == s*(t)) * attnmask
// ---------------------------------------------------------------------------
__global__ __launch_bounds__(256)
void kernelC(const float* __restrict__ latent, const float* __restrict__ mean,
             const int* __restrict__ mellen, float* __restrict__ out)
{
    const int RES4 = CB * CT * CN / 4;           // 655360
    const int TOT4 = RES4 + CB * CT * CS / 4;    // 2752512
    int i = blockIdx.x * blockDim.x + threadIdx.x;
    if (i >= TOT4) return;
    float4* out4 = (float4*)out;

    if (i < RES4) {
        int f  = i << 2;
        int bt = f / CN;
        int n  = f - bt * CN;
        int b  = bt >> 10;
        int t  = bt & (CT - 1);
        float4 r = ((const float4*)latent)[i];
        if (t < __ldg(&mellen[b])) {
            int sidx = g_idx[bt];
            float4 mv = *(const float4*)(mean + ((size_t)(b * CS + sidx)) * CN + n);
            r.x -= mv.x; r.y -= mv.y; r.z -= mv.z; r.w -= mv.w;
        }
        out4[i] = r;
    } else {
        int f  = (i - RES4) << 2;
        int bt = f >> 8;                 // / CS
        int s0 = f & (CS - 1);
        int b  = bt >> 10;
        int t  = bt & (CT - 1);
        float4 v = make_float4(0.f, 0.f, 0.f, 0.f);
        if (t < __ldg(&mellen[b])) {
            int sidx = g_idx[bt];        // always < textlen[b], so textmask == 1
            v.x = (sidx == s0)     ? 1.f : 0.f;
            v.y = (sidx == s0 + 1) ? 1.f : 0.f;
            v.z = (sidx == s0 + 2) ? 1.f : 0.f;
            v.w = (sidx == s0 + 3) ? 1.f : 0.f;
        }
        out4[i] = v;
    }
}

extern "C" void kernel_launch(void* const* d_in, const int* in_sizes, int n_in,
                              void* d_out, int out_size)
{
    const float* latent  = (const float*)d_in[0];   // [32,1024,80]
    const float* mean    = (const float*)d_in[1];   // [32,256,80]
    const int*   textlen = (const int*)d_in[2];     // [32]
    const int*   mellen  = (const int*)d_in[3];     // [32]
    float* out = (float*)d_out;                     // residual (B*T*N) ++ attn (B*T*S)

    const size_t shA = (size_t)(CN * (CS + 1) + CN * (TTILE + 1) + CS + TTILE) * sizeof(float);
    cudaFuncSetAttribute(kernelA, cudaFuncAttributeMaxDynamicSharedMemorySize, (int)shA);

    kernelA<<<CB * (CT / TTILE), 256, shA>>>(latent, mean, textlen, mellen);
    kernelB<<<CB, 32>>>(textlen, mellen);

    const int TOT4 = (CB * CT * CN + CB * CT * CS) / 4;
    kernelC<<<(TOT4 + 255) / 256, 256>>>(latent, mean, mellen, out);
}